// round 10
// baseline (speedup 1.0000x reference)
#include <cuda_runtime.h>

#define CC    256
#define LAGS  256
#define BATCH 64
#define DEC   32
#define TTOT  543
#define HID   512
#define NBC   256
#define NGRP  16
#define NBAR  8

typedef unsigned long long ull;

// Persistent scratch (no allocations allowed). No zero-init required for the
// filter buffers: every read is predicated to the valid tap range or written
// first. Barrier words are zero-initialized by the loader; g_gen is a
// monotonically increasing epoch that survives graph replays.
__device__ float g_PA[4 * LAGS * CC];
__device__ float g_PB[4 * LAGS * CC];
__device__ float g_bA[CC];
__device__ float g_bB[CC];
__device__ float g_GH[LAGS * HID];   // GH[tau][h] = sum_c Weff[c,tau]*W1[c,h]
__device__ float g_Ec[HID];          // b1 + beff^T W1
__device__ float g_E[BATCH * DEC * HID];
__device__ unsigned g_cnt[NGRP * 32];
__device__ unsigned g_rel[NGRP * 32];
__device__ unsigned g_root;
__device__ unsigned g_gen;

__device__ __forceinline__ ull pk2(float x, float y) {
    ull r;
    asm("mov.b64 %0, {%1, %2};" : "=l"(r) : "f"(x), "f"(y));
    return r;
}
__device__ __forceinline__ void upk2(float& x, float& y, ull v) {
    asm("mov.b64 {%0, %1}, %2;" : "=f"(x), "=f"(y) : "l"(v));
}
__device__ __forceinline__ ull fma2(ull a, ull b, ull c) {
    ull d;
    asm("fma.rn.f32x2 %0, %1, %2, %3;" : "=l"(d) : "l"(a), "l"(b), "l"(c));
    return d;
}

__device__ __forceinline__ unsigned ld_acq(unsigned* p) {
    unsigned v;
    asm volatile("ld.acquire.gpu.global.u32 %0, [%1];"
                 : "=r"(v) : "l"(p) : "memory");
    return v;
}
__device__ __forceinline__ unsigned atom_add_ar(unsigned* p, unsigned v) {
    unsigned o;
    asm volatile("atom.acq_rel.gpu.global.add.u32 %0, [%1], %2;"
                 : "=r"(o) : "l"(p), "r"(v) : "memory");
    return o;
}
__device__ __forceinline__ void st_rel(unsigned* p, unsigned v) {
    asm volatile("st.release.gpu.global.u32 [%0], %1;"
                 :: "l"(p), "r"(v) : "memory");
}

// Hierarchical grid barrier: 2-level arrival, 16 per-group release words
// (<=16 pollers per line instead of 256 on one line).
__device__ __forceinline__ void gridbar(int b, unsigned exp, bool last) {
    __syncthreads();
    if (threadIdx.x == 0) {
        int q = b >> 4;
        if (atom_add_ar(&g_cnt[q * 32], 1u) == 15u) {
            if (atom_add_ar(&g_root, 1u) == NGRP - 1) {
                #pragma unroll
                for (int qq = 0; qq < NGRP; qq++) g_cnt[qq * 32] = 0u;
                g_root = 0u;
                if (last) g_gen = exp;   // epoch for next replay
                #pragma unroll
                for (int qq = 0; qq < NGRP; qq++)
                    st_rel(&g_rel[qq * 32], exp);
            }
        }
        while ((int)(ld_acq(&g_rel[q * 32]) - exp) < 0) { }
    }
    __syncthreads();
}

// ---------------------------------------------------------------------------
// Persistent: 7 compose layers (layer 0 reads c0w directly; predicated
// source loads) + GH + Econst + E.
// ---------------------------------------------------------------------------
__global__ void __launch_bounds__(256, 2)
k_compose_all(const float* __restrict__ c0w, const float* __restrict__ c0b,
              const float* __restrict__ cw,  const float* __restrict__ cb,
              const float* __restrict__ w1,  const float* __restrict__ b1,
              const float* __restrict__ x) {
    __shared__ union {
        struct { float As[64][17], Ss[64][17], B0s[64][68], B1s[64][68]; } c;
        struct { float Wgs[16][132], w1s[128][34]; } g;
        struct { float xs[288], GHs[32][132]; } e;
    } smu;
    int b = blockIdx.x, t = threadIdx.x;
    unsigned base = 0;
    if (t == 0) base = *((volatile unsigned*)&g_gen);

    // ---- 7 layers: 16tau x 64co tiles, k-split 4, single 64-wide chunk ----
    int d = 2;
    for (int j = 0; j < 7; j++) {
        const float* Ps   = (j & 1) ? g_PB : g_PA;
        float*       Pd   = (j & 1) ? g_PA : g_PB;
        const float* srcb = (j & 1) ? g_bB : g_bA;   // unused when j==0
        float*       dstb = (j & 1) ? g_bA : g_bB;
        const float* w = cw + (size_t)j * CC * CC * 2;
        int R  = 4 << j;
        int TT = (R + 15) >> 4;          // 1,1,1,2,4,8,16
        int nuse = TT * 16;
        int Rsrc = 2 << j;               // valid source taps
        if (b < nuse) {
            int kp = b & 3, cot = (b >> 2) & 3, taut = b >> 4;
            int tau0 = taut * 16, co0 = cot * 64, k0 = kp * 64;
            int tl  = t & 15;
            int col = (t >> 4) * 4;
            ull acc0 = 0ull, acc1 = 0ull;
            const float2* wp2 = (const float2*)w;
            {
                #pragma unroll
                for (int e = 0; e < 16; e++) {
                    int idx = e * 256 + t;
                    int ci2 = idx & 63, co = idx >> 6;
                    float2 wv = wp2[(size_t)(co0 + co) * CC + k0 + ci2];
                    smu.c.B0s[ci2][co] = wv.x;
                    smu.c.B1s[ci2][co] = wv.y;
                }
                if (j == 0) {
                    #pragma unroll
                    for (int e = 0; e < 4; e++) {
                        int idx = e * 256 + t;
                        int kk = idx & 63, r = idx >> 6;
                        int ci = k0 + kk;
                        float av = 0.f, sv = 0.f;
                        if (r == 0)      av = c0w[ci * 2 + 1];
                        else if (r == 1) av = c0w[ci * 2 + 0];
                        int ts = r - 2;
                        if (ts == 0)      sv = c0w[ci * 2 + 1];
                        else if (ts == 1) sv = c0w[ci * 2 + 0];
                        smu.c.As[kk][r] = av;
                        smu.c.Ss[kk][r] = sv;
                    }
                } else {
                    #pragma unroll
                    for (int e = 0; e < 4; e++) {
                        int idx = e * 256 + t;
                        int kk = idx & 63, r = idx >> 6;
                        int ci = k0 + kk;
                        float av = 0.f, sv = 0.f;
                        int ta = tau0 + r;
                        if (ta < Rsrc) {
                            int ra = ta * CC + ci;
                            av = Ps[ra] + Ps[65536 + ra] + Ps[131072 + ra]
                               + Ps[196608 + ra];
                        }
                        int ts = ta - d;
                        if (ts >= 0 && ts < Rsrc) {
                            int rs = ts * CC + ci;
                            sv = Ps[rs] + Ps[65536 + rs] + Ps[131072 + rs]
                               + Ps[196608 + rs];
                        }
                        smu.c.As[kk][r] = av;
                        smu.c.Ss[kk][r] = sv;
                    }
                }
            }
            __syncthreads();
            #pragma unroll
            for (int kk = 0; kk < 64; kk++) {
                float a = smu.c.As[kk][tl], s = smu.c.Ss[kk][tl];
                ull a2 = pk2(a, a), s2 = pk2(s, s);
                ull p0 = *(const ull*)&smu.c.B1s[kk][col];
                ull p1 = *(const ull*)&smu.c.B1s[kk][col + 2];
                ull q0 = *(const ull*)&smu.c.B0s[kk][col];
                ull q1 = *(const ull*)&smu.c.B0s[kk][col + 2];
                acc0 = fma2(a2, p0, acc0);
                acc0 = fma2(s2, q0, acc0);
                acc1 = fma2(a2, p1, acc1);
                acc1 = fma2(s2, q1, acc1);
            }
            float c0, c1, c2, c3;
            upk2(c0, c1, acc0);
            upk2(c2, c3, acc1);
            float4 v = make_float4(c0, c1, c2, c3);
            *(float4*)&Pd[kp * 65536 + (tau0 + tl) * CC + co0 + col] = v;
        }
        // bias: blocks 224..255, one warp per output channel
        if (b >= 224) {
            int wid = t >> 5, lane = t & 31;
            int co = (b - 224) * 8 + wid;
            const float2* wp2b = (const float2*)w;
            float acc = 0.f;
            #pragma unroll
            for (int q = 0; q < 8; q++) {
                int ci = q * 32 + lane;
                float2 wv = wp2b[(size_t)co * CC + ci];
                float bp = (j == 0) ? c0b[ci] : srcb[ci];
                acc += (wv.x + wv.y) * bp;
            }
            #pragma unroll
            for (int off = 16; off > 0; off >>= 1)
                acc += __shfl_down_sync(0xffffffffu, acc, off);
            if (lane == 0) dstb[co] = acc + cb[(size_t)j * CC + co];
        }
        gridbar(b, base + 1 + j, false);
        d <<= 1;
    }

    // ---- GH[tau0..+15][h0..+31] from final partials (g_PB), 2 chunks ----
    {
        int tau0 = (b >> 4) * 16, h0 = (b & 15) * 32;
        int tg = t >> 4, h2 = (t & 15) * 2;
        ull acc = 0ull;
        #pragma unroll
        for (int cc2 = 0; cc2 < CC; cc2 += 128) {
            __syncthreads();
            #pragma unroll
            for (int e = 0; e < 8; e++) {
                int idx = e * 256 + t;
                int tr = idx >> 7, cl = idx & 127;
                int ra = (tau0 + tr) * CC + cc2 + cl;
                smu.g.Wgs[tr][cl] = g_PB[ra] + g_PB[65536 + ra]
                                  + g_PB[131072 + ra] + g_PB[196608 + ra];
            }
            #pragma unroll
            for (int e = 0; e < 16; e++) {
                int idx = e * 256 + t;
                int cr = idx >> 5, hl = idx & 31;
                smu.g.w1s[cr][hl] = w1[(size_t)(cc2 + cr) * HID + h0 + hl];
            }
            __syncthreads();
            #pragma unroll
            for (int ci = 0; ci < 128; ci++) {
                float wv = smu.g.Wgs[tg][ci];
                ull hv = *(const ull*)&smu.g.w1s[ci][h2];
                acc = fma2(pk2(wv, wv), hv, acc);
            }
        }
        float g0, g1;
        upk2(g0, g1, acc);
        g_GH[(tau0 + tg) * HID + h0 + h2]     = g0;
        g_GH[(tau0 + tg) * HID + h0 + h2 + 1] = g1;
    }

    // ---- Econst[h] = b1[h] + sum_c beff[c]*W1[c,h] (blocks 0..15, shfl) ----
    if (b < 16) {
        int wid = t >> 5, lane = t & 31;
        #pragma unroll
        for (int p = 0; p < 4; p++) {
            int h = b * 32 + p * 8 + wid;
            float acc = 0.f;
            #pragma unroll
            for (int q = 0; q < 8; q++) {
                int c = q * 32 + lane;
                acc += g_bB[c] * w1[(size_t)c * HID + h];
            }
            #pragma unroll
            for (int off = 16; off > 0; off >>= 1)
                acc += __shfl_down_sync(0xffffffffu, acc, off);
            if (lane == 0) g_Ec[h] = acc + b1[h];
        }
    }
    gridbar(b, base + NBAR, true);

    // ---- E phase (f32x2): thread owns h-pair; 8 i per thread ----
    {
        int bb = b >> 2, ht = b & 3;
        int h0 = ht * 128;
        smu.e.xs[t] = x[bb * TTOT + 256 + t];
        if (t < 32) smu.e.xs[256 + t] = 0.f;
        int hp = (t & 63) * 2, ig = t >> 6;
        ull acc[8];
        #pragma unroll
        for (int r = 0; r < 8; r++) acc[r] = 0ull;

        for (int tc = 0; tc < LAGS; tc += 32) {
            __syncthreads();
            #pragma unroll
            for (int e = 0; e < 16; e++) {
                int idx = e * 256 + t;
                int row = idx >> 7, col = idx & 127;
                smu.e.GHs[row][col] = g_GH[(tc + row) * HID + h0 + col];
            }
            __syncthreads();
            float xw[39];
            int base2 = 255 + ig * 8 - tc - 31;
            #pragma unroll
            for (int q = 0; q < 39; q++) xw[q] = smu.e.xs[base2 + q];
            #pragma unroll
            for (int tt = 0; tt < 32; tt++) {
                ull g = *(const ull*)&smu.e.GHs[tt][hp];
                #pragma unroll
                for (int r = 0; r < 8; r++) {
                    float xv = xw[r + 31 - tt];
                    acc[r] = fma2(g, pk2(xv, xv), acc[r]);
                }
            }
        }
        float e0, e1;
        float ec0 = g_Ec[h0 + hp], ec1 = g_Ec[h0 + hp + 1];
        #pragma unroll
        for (int r = 0; r < 8; r++) {
            upk2(e0, e1, acc[r]);
            float2 v = make_float2(e0 + ec0, e1 + ec1);
            *(float2*)&g_E[(size_t)(bb * DEC + ig * 8 + r) * HID + h0 + hp] = v;
        }
    }
}

// ---------------------------------------------------------------------------
// Decode: 512 thr/block, 1 h per thread, fully register-resident.
// ---------------------------------------------------------------------------
__global__ void __launch_bounds__(512, 1)
k_decode(const float* __restrict__ w2, const float* __restrict__ b2,
         float* __restrict__ out) {
    __shared__ float red[2][16];
    int t = threadIdx.x, b = blockIdx.x;
    int wid = t >> 5, lane = t & 31;
    float a[DEC];
    const float* Ef = g_E + (size_t)b * DEC * HID;
    #pragma unroll
    for (int i = 0; i < DEC; i++) a[i] = Ef[i * HID + t];
    float Gd[31];
    #pragma unroll
    for (int dd = 0; dd < 31; dd++) Gd[dd] = g_GH[dd * HID + t];
    float w2v = w2[t];
    float b2v = b2[0];
    #pragma unroll
    for (int i = 0; i < DEC; i++) {
        float p = fmaxf(a[i], 0.f) * w2v;
        #pragma unroll
        for (int off = 16; off > 0; off >>= 1)
            p += __shfl_down_sync(0xffffffffu, p, off);
        if (lane == 0) red[i & 1][wid] = p;
        __syncthreads();
        float4 r0 = *(const float4*)&red[i & 1][0];
        float4 r1 = *(const float4*)&red[i & 1][4];
        float4 r2 = *(const float4*)&red[i & 1][8];
        float4 r3 = *(const float4*)&red[i & 1][12];
        float s0 = (r0.x + r0.y) + (r0.z + r0.w);
        float s1 = (r1.x + r1.y) + (r1.z + r1.w);
        float s2 = (r2.x + r2.y) + (r2.z + r2.w);
        float s3 = (r3.x + r3.y) + (r3.z + r3.w);
        float o = b2v + ((s0 + s1) + (s2 + s3));
        if (t == 0) out[b * DEC + i] = o;
        #pragma unroll
        for (int ii = i + 1; ii < DEC; ii++)
            a[ii] += Gd[ii - 1 - i] * o;
    }
}

// ---------------------------------------------------------------------------
extern "C" void kernel_launch(void* const* d_in, const int* in_sizes, int n_in,
                              void* d_out, int out_size) {
    const float* x   = (const float*)d_in[0];
    const float* c0w = (const float*)d_in[1];
    const float* c0b = (const float*)d_in[2];
    const float* cw  = (const float*)d_in[3];
    const float* cb  = (const float*)d_in[4];
    const float* w1  = (const float*)d_in[5];
    const float* b1  = (const float*)d_in[6];
    const float* w2  = (const float*)d_in[7];
    const float* b2  = (const float*)d_in[8];
    float* out = (float*)d_out;

    k_compose_all<<<NBC, 256>>>(c0w, c0b, cw, cb, w1, b1, x);
    k_decode<<<BATCH, 512>>>(w2, b2, out);
}

// round 12
// speedup vs baseline: 1.3418x; 1.3418x over previous
#include <cuda_runtime.h>

#define CC    256
#define LAGS  256
#define BATCH 64
#define DEC   32
#define TTOT  543
#define HID   512
#define NBC   256
#define NGRP  16

typedef unsigned long long ull;

// Persistent scratch (no allocations allowed). No zero-init required for the
// filter buffers: every read is predicated to the valid tap range or written
// first.
__device__ float g_PA[4 * LAGS * CC];
__device__ float g_PB[4 * LAGS * CC];
__device__ float g_bA[CC];
__device__ float g_bB[CC];
__device__ float g_GH[LAGS * HID];   // GH[tau][h] = sum_c Weff[c,tau]*W1[c,h]
__device__ float g_Ec[HID];          // b1 + beff^T W1
__device__ float g_E[BATCH * DEC * HID];
__device__ float g_sink;             // DCE-defeat for the L2 warm-up reads
__device__ unsigned g_cnt[NGRP * 32];
__device__ unsigned g_root;
__device__ volatile unsigned g_gen;

__device__ __forceinline__ ull pk2(float x, float y) {
    ull r;
    asm("mov.b64 %0, {%1, %2};" : "=l"(r) : "f"(x), "f"(y));
    return r;
}
__device__ __forceinline__ void upk2(float& x, float& y, ull v) {
    asm("mov.b64 {%0, %1}, %2;" : "=f"(x), "=f"(y) : "l"(v));
}
__device__ __forceinline__ ull fma2(ull a, ull b, ull c) {
    ull d;
    asm("fma.rn.f32x2 %0, %1, %2, %3;" : "=l"(d) : "l"(a), "l"(b), "l"(c));
    return d;
}

// R9 barrier (measured-best): 2-level arrival atomics, single volatile
// generation word for release.
__device__ __forceinline__ void gridbar(int b) {
    __syncthreads();
    if (threadIdx.x == 0) {
        unsigned gen = g_gen;
        __threadfence();
        bool last = false;
        if (atomicAdd(&g_cnt[(b >> 4) * 32], 1u) == 15u) {
            if (atomicAdd(&g_root, 1u) == NGRP - 1) last = true;
        }
        if (last) {
            #pragma unroll
            for (int q = 0; q < NGRP; q++) g_cnt[q * 32] = 0u;
            g_root = 0u;
            __threadfence();
            g_gen = gen + 1;
        } else {
            while (g_gen == gen) { }
            __threadfence();
        }
    }
    __syncthreads();
}

// ---------------------------------------------------------------------------
// Persistent: L2 warm-up (idle blocks) + 7 compose layers + GH + Econst + E.
// ---------------------------------------------------------------------------
__global__ void __launch_bounds__(256, 2)
k_compose_all(const float* __restrict__ c0w, const float* __restrict__ c0b,
              const float* __restrict__ cw,  const float* __restrict__ cb,
              const float* __restrict__ w1,  const float* __restrict__ b1,
              const float* __restrict__ x) {
    __shared__ union {
        struct { float As[64][17], Ss[64][17], B0s[64][68], B1s[64][68]; } c;
        struct { float Wgs[16][132], w1s[128][34]; } g;
        struct { float xs[288], GHs[32][132]; } e;
    } smu;
    int b = blockIdx.x, t = threadIdx.x;

    // ---- L2 warm-up: blocks 64..255 stream cw (layers 1..6) + w1 once ----
    // Runs concurrently with layer 0 (worker blocks 0..15, bias 224..255).
    if (b >= 64) {
        int bi = b - 64;                       // 0..191
        const float4* s4 = (const float4*)(cw + (size_t)CC * CC * 2);
        const int tot4 = 6 * CC * CC * 2 / 4;  // layers 1..6: 196608 float4
        float acc = 0.f;
        for (int idx = bi * 256 + t; idx < tot4; idx += 192 * 256) {
            float4 v = s4[idx];
            acc += v.x + v.y + v.z + v.w;
        }
        const float4* w14 = (const float4*)w1;
        for (int idx = bi * 256 + t; idx < CC * HID / 4; idx += 192 * 256) {
            float4 v = w14[idx];
            acc += v.x + v.y + v.z + v.w;
        }
        // never-taken guarded store keeps the loads live (acc is finite and
        // fminf of finite with 0 can't be exactly this sentinel bit pattern)
        if (__float_as_uint(fminf(acc, 0.f)) == 0x7f800123u)
            g_sink = acc;
    }

    // ---- 7 layers: 16tau x 64co tiles, k-split 4, single 64-wide chunk ----
    int d = 2;
    for (int j = 0; j < 7; j++) {
        const float* Ps   = (j & 1) ? g_PB : g_PA;
        float*       Pd   = (j & 1) ? g_PA : g_PB;
        const float* srcb = (j & 1) ? g_bB : g_bA;   // unused when j==0
        float*       dstb = (j & 1) ? g_bA : g_bB;
        const float* w = cw + (size_t)j * CC * CC * 2;
        int R  = 4 << j;
        int TT = (R + 15) >> 4;          // 1,1,1,2,4,8,16
        int nuse = TT * 16;
        int Rsrc = 2 << j;               // valid source taps
        if (b < nuse) {
            int kp = b & 3, cot = (b >> 2) & 3, taut = b >> 4;
            int tau0 = taut * 16, co0 = cot * 64, k0 = kp * 64;
            int tl  = t & 15;
            int col = (t >> 4) * 4;
            ull acc0 = 0ull, acc1 = 0ull;
            const float2* wp2 = (const float2*)w;
            {
                #pragma unroll
                for (int e = 0; e < 16; e++) {
                    int idx = e * 256 + t;
                    int ci2 = idx & 63, co = idx >> 6;
                    float2 wv = wp2[(size_t)(co0 + co) * CC + k0 + ci2];
                    smu.c.B0s[ci2][co] = wv.x;
                    smu.c.B1s[ci2][co] = wv.y;
                }
                if (j == 0) {
                    #pragma unroll
                    for (int e = 0; e < 4; e++) {
                        int idx = e * 256 + t;
                        int kk = idx & 63, r = idx >> 6;
                        int ci = k0 + kk;
                        float av = 0.f, sv = 0.f;
                        if (r == 0)      av = c0w[ci * 2 + 1];
                        else if (r == 1) av = c0w[ci * 2 + 0];
                        int ts = r - 2;
                        if (ts == 0)      sv = c0w[ci * 2 + 1];
                        else if (ts == 1) sv = c0w[ci * 2 + 0];
                        smu.c.As[kk][r] = av;
                        smu.c.Ss[kk][r] = sv;
                    }
                } else {
                    #pragma unroll
                    for (int e = 0; e < 4; e++) {
                        int idx = e * 256 + t;
                        int kk = idx & 63, r = idx >> 6;
                        int ci = k0 + kk;
                        float av = 0.f, sv = 0.f;
                        int ta = tau0 + r;
                        if (ta < Rsrc) {
                            int ra = ta * CC + ci;
                            av = Ps[ra] + Ps[65536 + ra] + Ps[131072 + ra]
                               + Ps[196608 + ra];
                        }
                        int ts = ta - d;
                        if (ts >= 0 && ts < Rsrc) {
                            int rs = ts * CC + ci;
                            sv = Ps[rs] + Ps[65536 + rs] + Ps[131072 + rs]
                               + Ps[196608 + rs];
                        }
                        smu.c.As[kk][r] = av;
                        smu.c.Ss[kk][r] = sv;
                    }
                }
            }
            __syncthreads();
            #pragma unroll
            for (int kk = 0; kk < 64; kk++) {
                float a = smu.c.As[kk][tl], s = smu.c.Ss[kk][tl];
                ull a2 = pk2(a, a), s2 = pk2(s, s);
                ull p0 = *(const ull*)&smu.c.B1s[kk][col];
                ull p1 = *(const ull*)&smu.c.B1s[kk][col + 2];
                ull q0 = *(const ull*)&smu.c.B0s[kk][col];
                ull q1 = *(const ull*)&smu.c.B0s[kk][col + 2];
                acc0 = fma2(a2, p0, acc0);
                acc0 = fma2(s2, q0, acc0);
                acc1 = fma2(a2, p1, acc1);
                acc1 = fma2(s2, q1, acc1);
            }
            float c0, c1, c2, c3;
            upk2(c0, c1, acc0);
            upk2(c2, c3, acc1);
            float4 v = make_float4(c0, c1, c2, c3);
            *(float4*)&Pd[kp * 65536 + (tau0 + tl) * CC + co0 + col] = v;
        }
        // bias: blocks 224..255, one warp per output channel
        if (b >= 224) {
            int wid = t >> 5, lane = t & 31;
            int co = (b - 224) * 8 + wid;
            const float2* wp2b = (const float2*)w;
            float acc = 0.f;
            #pragma unroll
            for (int q = 0; q < 8; q++) {
                int ci = q * 32 + lane;
                float2 wv = wp2b[(size_t)co * CC + ci];
                float bp = (j == 0) ? c0b[ci] : srcb[ci];
                acc += (wv.x + wv.y) * bp;
            }
            #pragma unroll
            for (int off = 16; off > 0; off >>= 1)
                acc += __shfl_down_sync(0xffffffffu, acc, off);
            if (lane == 0) dstb[co] = acc + cb[(size_t)j * CC + co];
        }
        gridbar(b);
        d <<= 1;
    }

    // ---- GH[tau0..+15][h0..+31] from final partials (g_PB), 2 chunks ----
    {
        int tau0 = (b >> 4) * 16, h0 = (b & 15) * 32;
        int tg = t >> 4, h2 = (t & 15) * 2;
        ull acc = 0ull;
        #pragma unroll
        for (int cc2 = 0; cc2 < CC; cc2 += 128) {
            __syncthreads();
            #pragma unroll
            for (int e = 0; e < 8; e++) {
                int idx = e * 256 + t;
                int tr = idx >> 7, cl = idx & 127;
                int ra = (tau0 + tr) * CC + cc2 + cl;
                smu.g.Wgs[tr][cl] = g_PB[ra] + g_PB[65536 + ra]
                                  + g_PB[131072 + ra] + g_PB[196608 + ra];
            }
            #pragma unroll
            for (int e = 0; e < 16; e++) {
                int idx = e * 256 + t;
                int cr = idx >> 5, hl = idx & 31;
                smu.g.w1s[cr][hl] = w1[(size_t)(cc2 + cr) * HID + h0 + hl];
            }
            __syncthreads();
            #pragma unroll
            for (int ci = 0; ci < 128; ci++) {
                float wv = smu.g.Wgs[tg][ci];
                ull hv = *(const ull*)&smu.g.w1s[ci][h2];
                acc = fma2(pk2(wv, wv), hv, acc);
            }
        }
        float g0, g1;
        upk2(g0, g1, acc);
        g_GH[(tau0 + tg) * HID + h0 + h2]     = g0;
        g_GH[(tau0 + tg) * HID + h0 + h2 + 1] = g1;
    }

    // ---- Econst[h] = b1[h] + sum_c beff[c]*W1[c,h] (blocks 0..15, shfl) ----
    if (b < 16) {
        int wid = t >> 5, lane = t & 31;
        #pragma unroll
        for (int p = 0; p < 4; p++) {
            int h = b * 32 + p * 8 + wid;
            float acc = 0.f;
            #pragma unroll
            for (int q = 0; q < 8; q++) {
                int c = q * 32 + lane;
                acc += g_bB[c] * w1[(size_t)c * HID + h];
            }
            #pragma unroll
            for (int off = 16; off > 0; off >>= 1)
                acc += __shfl_down_sync(0xffffffffu, acc, off);
            if (lane == 0) g_Ec[h] = acc + b1[h];
        }
    }
    gridbar(b);

    // ---- E phase (f32x2): thread owns h-pair; 8 i per thread ----
    {
        int bb = b >> 2, ht = b & 3;
        int h0 = ht * 128;
        smu.e.xs[t] = x[bb * TTOT + 256 + t];
        if (t < 32) smu.e.xs[256 + t] = 0.f;
        int hp = (t & 63) * 2, ig = t >> 6;
        ull acc[8];
        #pragma unroll
        for (int r = 0; r < 8; r++) acc[r] = 0ull;

        for (int tc = 0; tc < LAGS; tc += 32) {
            __syncthreads();
            #pragma unroll
            for (int e = 0; e < 16; e++) {
                int idx = e * 256 + t;
                int row = idx >> 7, col = idx & 127;
                smu.e.GHs[row][col] = g_GH[(tc + row) * HID + h0 + col];
            }
            __syncthreads();
            float xw[39];
            int base2 = 255 + ig * 8 - tc - 31;
            #pragma unroll
            for (int q = 0; q < 39; q++) xw[q] = smu.e.xs[base2 + q];
            #pragma unroll
            for (int tt = 0; tt < 32; tt++) {
                ull g = *(const ull*)&smu.e.GHs[tt][hp];
                #pragma unroll
                for (int r = 0; r < 8; r++) {
                    float xv = xw[r + 31 - tt];
                    acc[r] = fma2(g, pk2(xv, xv), acc[r]);
                }
            }
        }
        float e0, e1;
        float ec0 = g_Ec[h0 + hp], ec1 = g_Ec[h0 + hp + 1];
        #pragma unroll
        for (int r = 0; r < 8; r++) {
            upk2(e0, e1, acc[r]);
            float2 v = make_float2(e0 + ec0, e1 + ec1);
            *(float2*)&g_E[(size_t)(bb * DEC + ig * 8 + r) * HID + h0 + hp] = v;
        }
    }
}

// ---------------------------------------------------------------------------
// Decode: 512 thr/block, 1 h per thread, fully register-resident.
// ---------------------------------------------------------------------------
__global__ void __launch_bounds__(512, 1)
k_decode(const float* __restrict__ w2, const float* __restrict__ b2,
         float* __restrict__ out) {
    __shared__ float red[2][16];
    int t = threadIdx.x, b = blockIdx.x;
    int wid = t >> 5, lane = t & 31;
    float a[DEC];
    const float* Ef = g_E + (size_t)b * DEC * HID;
    #pragma unroll
    for (int i = 0; i < DEC; i++) a[i] = Ef[i * HID + t];
    float Gd[31];
    #pragma unroll
    for (int dd = 0; dd < 31; dd++) Gd[dd] = g_GH[dd * HID + t];
    float w2v = w2[t];
    float b2v = b2[0];
    #pragma unroll
    for (int i = 0; i < DEC; i++) {
        float p = fmaxf(a[i], 0.f) * w2v;
        #pragma unroll
        for (int off = 16; off > 0; off >>= 1)
            p += __shfl_down_sync(0xffffffffu, p, off);
        if (lane == 0) red[i & 1][wid] = p;
        __syncthreads();
        float4 r0 = *(const float4*)&red[i & 1][0];
        float4 r1 = *(const float4*)&red[i & 1][4];
        float4 r2 = *(const float4*)&red[i & 1][8];
        float4 r3 = *(const float4*)&red[i & 1][12];
        float s0 = (r0.x + r0.y) + (r0.z + r0.w);
        float s1 = (r1.x + r1.y) + (r1.z + r1.w);
        float s2 = (r2.x + r2.y) + (r2.z + r2.w);
        float s3 = (r3.x + r3.y) + (r3.z + r3.w);
        float o = b2v + ((s0 + s1) + (s2 + s3));
        if (t == 0) out[b * DEC + i] = o;
        #pragma unroll
        for (int ii = i + 1; ii < DEC; ii++)
            a[ii] += Gd[ii - 1 - i] * o;
    }
}

// ---------------------------------------------------------------------------
extern "C" void kernel_launch(void* const* d_in, const int* in_sizes, int n_in,
                              void* d_out, int out_size) {
    const float* x   = (const float*)d_in[0];
    const float* c0w = (const float*)d_in[1];
    const float* c0b = (const float*)d_in[2];
    const float* cw  = (const float*)d_in[3];
    const float* cb  = (const float*)d_in[4];
    const float* w1  = (const float*)d_in[5];
    const float* b1  = (const float*)d_in[6];
    const float* w2  = (const float*)d_in[7];
    const float* b2  = (const float*)d_in[8];
    float* out = (float*)d_out;

    k_compose_all<<<NBC, 256>>>(c0w, c0b, cw, cb, w1, b1, x);
    k_decode<<<BATCH, 512>>>(w2, b2, out);
}